// round 10
// baseline (speedup 1.0000x reference)
#include <cuda_runtime.h>

// quadLayer: out[b,h,w, c*512 + a*32 + f] =
//   sum_m p[a][m] W1[c][m][f] + sum_{m1,m2} p[a][m1] p[a][m2] W2[c][m1*4+m2][f]
// p[a][mm] = x[b, 2h+((a>>2)>>1), 2w+((a>>2)&1), 4*(a&3)+mm]  (one float4 of x).
//
// R10: Horner symmetric quadratic with f-PAIR f32x2 packing and one c-plane
// per thread: thread (c, fp) owns f = 2fp, 2fp+1. Weights {w_f, w_f+1} =
// 14 u64 = 28 regs; p values duplicated {p,p} in smem (2 broadcast LDS.128
// per a); 15 FFMA2 + 1 STG.64 per (pix, a). Target <=63 regs -> 4 CTAs/SM.

#define NPIX 4
#define THREADS 256

__device__ __forceinline__ unsigned long long pack2(float lo, float hi) {
    unsigned long long r;
    asm("mov.b64 %0, {%1,%2};" : "=l"(r) : "f"(lo), "f"(hi));
    return r;
}

__device__ __forceinline__ void fma2(unsigned long long &d,
                                     unsigned long long a,
                                     unsigned long long b) {
    asm("fma.rn.f32x2 %0, %1, %2, %0;" : "+l"(d) : "l"(a), "l"(b));
}

__device__ __forceinline__ unsigned long long fma2n(unsigned long long a,
                                                    unsigned long long b,
                                                    unsigned long long c) {
    unsigned long long d;
    asm("fma.rn.f32x2 %0, %1, %2, %3;" : "=l"(d) : "l"(a), "l"(b), "l"(c));
    return d;
}

__device__ __forceinline__ unsigned long long mul2(unsigned long long a,
                                                   unsigned long long b) {
    unsigned long long d;
    asm("mul.rn.f32x2 %0, %1, %2;" : "=l"(d) : "l"(a), "l"(b));
    return d;
}

__device__ __forceinline__ unsigned long long add2(unsigned long long a,
                                                   unsigned long long b) {
    unsigned long long r;
    asm("add.rn.f32x2 %0, %1, %2;" : "=l"(r) : "l"(a), "l"(b));
    return r;
}

__global__ void __launch_bounds__(THREADS, 4)
quad_kernel(const float* __restrict__ x,
            const float* __restrict__ W1,
            const float* __restrict__ W2,
            float* __restrict__ out)
{
    // duplicated base values: NPIX * 16 a * 4 m * 2 dup floats = 2 KB
    __shared__ __align__(16) float pbase[NPIX * 16 * 4 * 2];

    const int t  = threadIdx.x;
    const int c  = t >> 4;    // 0..15
    const int fp = t & 15;    // 0..15 -> f = 2fp, 2fp+1
    const int f0 = 2 * fp;

    // ---- weights, f-pair packed: lin[m] = {W1[c,m,f0], W1[c,m,f0+1]},
    //      q[k] = symmetric-fold of W2 (m1<=m2), same packing ----
    unsigned long long lin[4], q[10];
    {
        const float* w1c = W1 + c * 128 + f0;
        const float* w2c = W2 + c * 512 + f0;
#pragma unroll
        for (int m = 0; m < 4; m++)
            lin[m] = pack2(w1c[m * 32], w1c[m * 32 + 1]);
        int k = 0;
#pragma unroll
        for (int m1 = 0; m1 < 4; m1++)
#pragma unroll
            for (int m2 = m1; m2 < 4; m2++) {
                float a0, a1;
                if (m1 == m2) {
                    a0 = w2c[(5 * m1) * 32];
                    a1 = w2c[(5 * m1) * 32 + 1];
                } else {
                    const int qa = (m1 * 4 + m2) * 32, qb = (m2 * 4 + m1) * 32;
                    a0 = w2c[qa] + w2c[qb];
                    a1 = w2c[qa + 1] + w2c[qb + 1];
                }
                q[k++] = pack2(a0, a1);
            }
    }

    // ---- base-value build: one thread per (pix, a), duplicated ----
    if (t < NPIX * 16) {
        const int pix = t >> 4;
        const int a   = t & 15;
        const int g   = blockIdx.x * NPIX + pix;   // global pixel id
        const int b   = g >> 10;
        const int h   = (g >> 5) & 31;
        const int wc  = g & 31;
        const int m   = a >> 2;
        const int i   = m >> 1;
        const int j   = m & 1;
        const int ch0 = (a & 3) * 4;
        const float4 v = *reinterpret_cast<const float4*>(
            x + (((b * 64 + 2 * h + i) * 64) + (2 * wc + j)) * 16 + ch0);
        float* fb = &pbase[(pix * 16 + a) * 8];
        fb[0] = v.x; fb[1] = v.x;
        fb[2] = v.y; fb[3] = v.y;
        fb[4] = v.z; fb[5] = v.z;
        fb[6] = v.w; fb[7] = v.w;
    }
    __syncthreads();

    float* op = out + (size_t)blockIdx.x * NPIX * 8192 + (size_t)(c * 512 + f0);
    unsigned int saddr = (unsigned int)__cvta_generic_to_shared(pbase);

#pragma unroll 1
    for (int pix = 0; pix < NPIX; pix++) {
#pragma unroll
        for (int a = 0; a < 16; a++) {
            unsigned long long pp0, pp1, pp2, pp3;
            asm("ld.shared.v2.u64 {%0,%1}, [%2];"
                : "=l"(pp0), "=l"(pp1) : "r"(saddr));
            asm("ld.shared.v2.u64 {%0,%1}, [%2];"
                : "=l"(pp2), "=l"(pp3) : "r"(saddr + 16));
            saddr += 32;

            // q idx: (0,0)=0 (0,1)=1 (0,2)=2 (0,3)=3 (1,1)=4 (1,2)=5 (1,3)=6
            //        (2,2)=7 (2,3)=8 (3,3)=9
            unsigned long long t0 = fma2n(pp0, q[0], lin[0]);
            unsigned long long t1 = fma2n(pp1, q[4], lin[1]);
            unsigned long long t2 = fma2n(pp2, q[7], lin[2]);
            unsigned long long t3 = fma2n(pp3, q[9], lin[3]);
            fma2(t0, pp1, q[1]);
            fma2(t1, pp2, q[5]);
            fma2(t2, pp3, q[8]);
            fma2(t0, pp2, q[2]);
            fma2(t1, pp3, q[6]);
            fma2(t0, pp3, q[3]);
            unsigned long long s0 = mul2(pp0, t0);
            unsigned long long s1 = mul2(pp1, t1);
            fma2(s0, pp2, t2);
            fma2(s1, pp3, t3);
            const unsigned long long s = add2(s0, s1);

            float lo, hi;
            asm("mov.b64 {%0,%1}, %2;" : "=f"(lo), "=f"(hi) : "l"(s));
            asm("st.global.cs.v2.f32 [%0], {%1,%2};"
                :: "l"(op + a * 32), "f"(lo), "f"(hi) : "memory");
        }
        op += 8192;
    }
}

extern "C" void kernel_launch(void* const* d_in, const int* in_sizes, int n_in,
                              void* d_out, int out_size) {
    const float* x  = (const float*)d_in[0];
    const float* W1 = (const float*)d_in[1];
    const float* W2 = (const float*)d_in[2];
    float* out = (float*)d_out;
    quad_kernel<<<8192 / NPIX, THREADS>>>(x, W1, W2, out);
}